// round 2
// baseline (speedup 1.0000x reference)
#include <cuda_runtime.h>
#include <math.h>

#define N_ROWS 65536
#define D      512
#define NB     65536      // buckets for counting sort
#define NCHUNK 256
#define CHUNK  256

// ---------------- scratch (static device globals; no allocations) ----------
__device__ float    g_e2[N_ROWS], g_e3[N_ROWS];       // exp(cos sim) per row
__device__ unsigned g_hist[NB], g_cnt[NB], g_off[NB]; // bucket histogram / counters / offsets
__device__ int      g_bucketed[N_ROWS];               // row indices scattered into bucket slots
__device__ float    g_se2[N_ROWS], g_se3[N_ROWS];     // e values in ascending-ranking order
__device__ double   g_csum2[NCHUNK], g_csum3[NCHUNK]; // per-chunk sums
__device__ double   g_coff2[NCHUNK], g_coff3[NCHUNK]; // exclusive chunk offsets
__device__ double   g_tot2, g_tot3;                   // totals
__device__ double   g_ls2[NCHUNK], g_ls3[NCHUNK];     // per-chunk sum of logs
__device__ float    g_n2, g_n3;                       // ||o2||, ||o3||

__device__ __forceinline__ unsigned bucket_of(float k) {
    k = fminf(fmaxf(k, 0.0f), 0.999999f);
    unsigned b = (unsigned)(k * 65536.0f);
    return b > 65535u ? 65535u : b;
}

// K0: zero histogram/counters; compute ||o2||, ||o3||. One block of 1024.
__global__ void k0_init(const float* __restrict__ o2, const float* __restrict__ o3) {
    int t = threadIdx.x;
    for (int j = t; j < NB; j += 1024) { g_hist[j] = 0u; g_cnt[j] = 0u; }
    __shared__ float s2[1024], s3[1024];
    float a2 = 0.f, a3 = 0.f;
    if (t < D) { float v2 = o2[t], v3 = o3[t]; a2 = v2 * v2; a3 = v3 * v3; }
    s2[t] = a2; s3[t] = a3; __syncthreads();
    for (int o = 512; o > 0; o >>= 1) {
        if (t < o) { s2[t] += s2[t + o]; s3[t] += s3[t + o]; }
        __syncthreads();
    }
    if (t == 0) { g_n2 = sqrtf(s2[0]); g_n3 = sqrtf(s3[0]); }
}

// K1: per-row cos-sim -> exp; fused ranking histogram. 1 warp per row.
__global__ void k1_main(const float4* __restrict__ x,
                        const float4* __restrict__ o2,
                        const float4* __restrict__ o3,
                        const float*  __restrict__ rank) {
    __shared__ float4 so2[128], so3[128];
    int t = threadIdx.x;
    if (t < 128)       so2[t]       = o2[t];
    else if (t < 256)  so3[t - 128] = o3[t - 128];
    __syncthreads();

    int warp = t >> 5, lane = t & 31;
    int row = blockIdx.x * 8 + warp;                 // grid = 8192 blocks * 8 warps
    const float4* xr = x + (size_t)row * 128;

    float d2 = 0.f, d3 = 0.f, nn = 0.f;
#pragma unroll
    for (int k = 0; k < 4; k++) {
        float4 v = xr[lane + 32 * k];
        float4 a = so2[lane + 32 * k];
        float4 b = so3[lane + 32 * k];
        d2 += v.x * a.x + v.y * a.y + v.z * a.z + v.w * a.w;
        d3 += v.x * b.x + v.y * b.y + v.z * b.z + v.w * b.w;
        nn += v.x * v.x + v.y * v.y + v.z * v.z + v.w * v.w;
    }
#pragma unroll
    for (int o = 16; o > 0; o >>= 1) {
        d2 += __shfl_xor_sync(0xFFFFFFFFu, d2, o);
        d3 += __shfl_xor_sync(0xFFFFFFFFu, d3, o);
        nn += __shfl_xor_sync(0xFFFFFFFFu, nn, o);
    }
    if (lane == 0) {
        float nx = sqrtf(nn);
        float s2 = d2 / fmaxf(nx * g_n2, 1e-8f);
        float s3 = d3 / fmaxf(nx * g_n3, 1e-8f);
        g_e2[row] = expf(s2);
        g_e3[row] = expf(s3);
        atomicAdd(&g_hist[bucket_of(rank[row])], 1u);
    }
}

// K3: exclusive scan of the 65536-bin histogram. One block of 1024; 64 bins/thread.
__global__ void k3_scan_hist() {
    int t = threadIdx.x;
    int base = t * 64;
    unsigned s = 0;
    for (int j = 0; j < 64; j++) s += g_hist[base + j];
    __shared__ unsigned sh[1024];
    sh[t] = s; __syncthreads();
    for (int o = 1; o < 1024; o <<= 1) {
        unsigned add = (t >= o) ? sh[t - o] : 0u;
        __syncthreads();
        sh[t] += add;
        __syncthreads();
    }
    unsigned run = (t > 0) ? sh[t - 1] : 0u;
    for (int j = 0; j < 64; j++) {
        unsigned h = g_hist[base + j];
        g_off[base + j] = run;
        run += h;
    }
}

// K4: scatter row indices into bucket slots (order within bucket arbitrary).
__global__ void k4_scatter(const float* __restrict__ rank) {
    int i = blockIdx.x * blockDim.x + threadIdx.x;
    unsigned b = bucket_of(rank[i]);
    unsigned slot = g_off[b] + atomicAdd(&g_cnt[b], 1u);
    g_bucketed[slot] = i;
}

// K5: resolve within-bucket order by (key, idx) total order -> deterministic sorted e arrays.
__global__ void k5_place(const float* __restrict__ rank) {
    int b = blockIdx.x * blockDim.x + threadIdx.x;   // 65536 threads, 1 per bucket
    unsigned c = g_hist[b];
    if (c == 0) return;
    unsigned base = g_off[b];
    for (unsigned j = 0; j < c; j++) {
        int idx = g_bucketed[base + j];
        float kj = rank[idx];
        unsigned r = 0;
        for (unsigned l = 0; l < c; l++) {
            if (l == j) continue;
            int idl = g_bucketed[base + l];
            float kl = rank[idl];
            if (kl < kj || (kl == kj && idl < idx)) r++;
        }
        g_se2[base + r] = g_e2[idx];
        g_se3[base + r] = g_e3[idx];
    }
}

// K6: per-chunk double sums of sorted e arrays. 256 blocks x 256.
__global__ void k6_chunk_sums() {
    int blk = blockIdx.x, t = threadIdx.x;
    int i = blk * CHUNK + t;
    __shared__ double sh[CHUNK];
    sh[t] = (double)g_se2[i]; __syncthreads();
    for (int o = 128; o > 0; o >>= 1) { if (t < o) sh[t] += sh[t + o]; __syncthreads(); }
    if (t == 0) g_csum2[blk] = sh[0];
    __syncthreads();
    sh[t] = (double)g_se3[i]; __syncthreads();
    for (int o = 128; o > 0; o >>= 1) { if (t < o) sh[t] += sh[t + o]; __syncthreads(); }
    if (t == 0) g_csum3[blk] = sh[0];
}

// K7: exclusive scan of the 256 chunk sums (both arrays) + totals. One block of 256.
__global__ void k7_scan_chunks() {
    int t = threadIdx.x;
    __shared__ double sh[NCHUNK];
    double v = g_csum2[t];
    sh[t] = v; __syncthreads();
    for (int o = 1; o < NCHUNK; o <<= 1) {
        double add = (t >= o) ? sh[t - o] : 0.0;
        __syncthreads(); sh[t] += add; __syncthreads();
    }
    g_coff2[t] = sh[t] - v;
    if (t == NCHUNK - 1) g_tot2 = sh[t];
    __syncthreads();
    v = g_csum3[t];
    sh[t] = v; __syncthreads();
    for (int o = 1; o < NCHUNK; o <<= 1) {
        double add = (t >= o) ? sh[t - o] : 0.0;
        __syncthreads(); sh[t] += add; __syncthreads();
    }
    g_coff3[t] = sh[t] - v;
    if (t == NCHUNK - 1) g_tot3 = sh[t];
}

// K8: per-chunk inclusive scan + sum of logs. 256 blocks x 256.
__global__ void k8_logsum() {
    int blk = blockIdx.x, t = threadIdx.x;
    int i = blk * CHUNK + t;
    __shared__ double sh[CHUNK];

    // branch 2
    double v = (double)g_se2[i];
    sh[t] = v; __syncthreads();
    for (int o = 1; o < CHUNK; o <<= 1) {
        double add = (t >= o) ? sh[t - o] : 0.0;
        __syncthreads(); sh[t] += add; __syncthreads();
    }
    double l2 = log(g_coff2[blk] + sh[t]);
    __syncthreads();
    sh[t] = l2; __syncthreads();
    for (int o = 128; o > 0; o >>= 1) { if (t < o) sh[t] += sh[t + o]; __syncthreads(); }
    if (t == 0) g_ls2[blk] = sh[0];
    __syncthreads();

    // branch 3
    v = (double)g_se3[i];
    sh[t] = v; __syncthreads();
    for (int o = 1; o < CHUNK; o <<= 1) {
        double add = (t >= o) ? sh[t - o] : 0.0;
        __syncthreads(); sh[t] += add; __syncthreads();
    }
    double l3 = log(g_coff3[blk] + sh[t]);
    __syncthreads();
    sh[t] = l3; __syncthreads();
    for (int o = 128; o > 0; o >>= 1) { if (t < o) sh[t] += sh[t + o]; __syncthreads(); }
    if (t == 0) g_ls3[blk] = sh[0];
}

// K9: final reduce + write scalar. One block of 256.
// loss = N*log(tot2) - sum_k log(pref2[k]) + N*log(tot3) - sum_k log(pref3[k])
// (the k = N-1 term of the reference sum is exactly 0, so summing all k is equivalent)
__global__ void k9_final(float* __restrict__ out) {
    int t = threadIdx.x;
    __shared__ double sh[NCHUNK];
    sh[t] = g_ls2[t] + g_ls3[t]; __syncthreads();
    for (int o = 128; o > 0; o >>= 1) { if (t < o) sh[t] += sh[t + o]; __syncthreads(); }
    if (t == 0) {
        double loss = (double)N_ROWS * (log(g_tot2) + log(g_tot3)) - sh[0];
        out[0] = (float)loss;
    }
}

extern "C" void kernel_launch(void* const* d_in, const int* in_sizes, int n_in,
                              void* d_out, int out_size) {
    const float* o1   = (const float*)d_in[0];  // [65536, 512]
    const float* o2   = (const float*)d_in[1];  // [1, 512]
    const float* o3   = (const float*)d_in[2];  // [1, 512]
    const float* rank = (const float*)d_in[3];  // [65536]
    float* out = (float*)d_out;

    k0_init<<<1, 1024>>>(o2, o3);
    k1_main<<<N_ROWS / 8, 256>>>((const float4*)o1, (const float4*)o2,
                                 (const float4*)o3, rank);
    k3_scan_hist<<<1, 1024>>>();
    k4_scatter<<<N_ROWS / 256, 256>>>(rank);
    k5_place<<<NB / 256, 256>>>(rank);
    k6_chunk_sums<<<NCHUNK, CHUNK>>>();
    k7_scan_chunks<<<1, NCHUNK>>>();
    k8_logsum<<<NCHUNK, CHUNK>>>();
    k9_final<<<1, NCHUNK>>>(out);
}

// round 6
// speedup vs baseline: 2.1234x; 2.1234x over previous
#include <cuda_runtime.h>
#include <math.h>

#define N_ROWS 65536
#define D      512
#define NB     65536      // buckets for counting sort
#define NCHUNK 256
#define CHUNK  256

// ---------------- scratch (static device globals; no allocations) ----------
__device__ float    g_e2[N_ROWS], g_e3[N_ROWS];         // exp(cos sim) per row
__device__ unsigned g_hist[NB], g_cnt[NB], g_off[NB];   // histogram / counters / excl offsets
__device__ unsigned long long g_bsort[N_ROWS];          // packed (key_bits<<32)|idx per slot
__device__ float    g_se2[N_ROWS], g_se3[N_ROWS];       // e values, ascending-ranking order
__device__ double   g_csum2[NCHUNK], g_csum3[NCHUNK];   // per-chunk sums
__device__ double   g_part[NCHUNK];                     // per-chunk log-sum partials
__device__ float    g_n2, g_n3;                         // ||o2||, ||o3||
__device__ unsigned g_done;                             // last-block counter

__device__ __forceinline__ unsigned bucket_of(float k) {
    k = fminf(fmaxf(k, 0.0f), 0.999999f);
    unsigned b = (unsigned)(k * 65536.0f);
    return b > 65535u ? 65535u : b;
}

// K0: zero hist/cnt/done; block 0 computes ||o2||, ||o3||. grid 64 x 1024.
__global__ void __launch_bounds__(1024)
k0_init(const float4* __restrict__ o2, const float4* __restrict__ o3) {
    int t = threadIdx.x;
    unsigned gid = blockIdx.x * 1024u + t;
    g_hist[gid] = 0u;
    g_cnt[gid]  = 0u;
    if (blockIdx.x == 0) {
        if (t == 0) g_done = 0u;
        float a2 = 0.f, a3 = 0.f;
        if (t < 128) {
            float4 v = o2[t]; a2 = v.x*v.x + v.y*v.y + v.z*v.z + v.w*v.w;
            float4 w = o3[t]; a3 = w.x*w.x + w.y*w.y + w.z*w.z + w.w*w.w;
        }
#pragma unroll
        for (int o = 16; o > 0; o >>= 1) {
            a2 += __shfl_xor_sync(0xFFFFFFFFu, a2, o);
            a3 += __shfl_xor_sync(0xFFFFFFFFu, a3, o);
        }
        __shared__ float s2[32], s3[32];
        if ((t & 31) == 0) { s2[t >> 5] = a2; s3[t >> 5] = a3; }
        __syncthreads();
        if (t == 0) {
            float b2 = 0.f, b3 = 0.f;
            for (int j = 0; j < 4; j++) { b2 += s2[j]; b3 += s3[j]; }
            g_n2 = sqrtf(b2); g_n3 = sqrtf(b3);
        }
    }
}

// K1: per-row cos-sim -> exp; fused ranking histogram. 1 warp per row.
__global__ void __launch_bounds__(256)
k1_main(const float4* __restrict__ x,
        const float4* __restrict__ o2,
        const float4* __restrict__ o3,
        const float*  __restrict__ rank) {
    __shared__ float4 so2[128], so3[128];
    int t = threadIdx.x;
    if (t < 128)       so2[t]       = o2[t];
    else if (t < 256)  so3[t - 128] = o3[t - 128];
    __syncthreads();

    int warp = t >> 5, lane = t & 31;
    int row = blockIdx.x * 8 + warp;
    const float4* xr = x + (size_t)row * 128;

    float d2 = 0.f, d3 = 0.f, nn = 0.f;
#pragma unroll
    for (int k = 0; k < 4; k++) {
        float4 v = xr[lane + 32 * k];
        float4 a = so2[lane + 32 * k];
        float4 b = so3[lane + 32 * k];
        d2 += v.x * a.x + v.y * a.y + v.z * a.z + v.w * a.w;
        d3 += v.x * b.x + v.y * b.y + v.z * b.z + v.w * b.w;
        nn += v.x * v.x + v.y * v.y + v.z * v.z + v.w * v.w;
    }
#pragma unroll
    for (int o = 16; o > 0; o >>= 1) {
        d2 += __shfl_xor_sync(0xFFFFFFFFu, d2, o);
        d3 += __shfl_xor_sync(0xFFFFFFFFu, d3, o);
        nn += __shfl_xor_sync(0xFFFFFFFFu, nn, o);
    }
    if (lane == 0) {
        float nx = sqrtf(nn);
        float s2 = d2 / fmaxf(nx * g_n2, 1e-8f);
        float s3 = d3 / fmaxf(nx * g_n3, 1e-8f);
        g_e2[row] = expf(s2);
        g_e3[row] = expf(s3);
        atomicAdd(&g_hist[bucket_of(rank[row])], 1u);
    }
}

// K2: exclusive scan of the 65536-bin histogram. One block of 1024; 64 bins/thread.
// Two passes over the bins (second re-read hits L2) to keep register count low.
__global__ void __launch_bounds__(1024)
k2_scan_hist() {
    int t = threadIdx.x;
    const uint4* h4 = (const uint4*)g_hist;
    unsigned s = 0;
    for (int j = 0; j < 16; j++) {
        uint4 v = h4[t * 16 + j];
        s += v.x + v.y + v.z + v.w;
    }
    __shared__ unsigned sh[1024];
    sh[t] = s; __syncthreads();
    for (int o = 1; o < 1024; o <<= 1) {
        unsigned a = (t >= o) ? sh[t - o] : 0u;
        __syncthreads();
        sh[t] += a;
        __syncthreads();
    }
    unsigned run = (t > 0) ? sh[t - 1] : 0u;
    uint4* o4 = (uint4*)g_off;
    for (int j = 0; j < 16; j++) {
        uint4 v = h4[t * 16 + j];
        uint4 w;
        w.x = run; run += v.x;
        w.y = run; run += v.y;
        w.z = run; run += v.z;
        w.w = run; run += v.w;
        o4[t * 16 + j] = w;
    }
}

// K3: scatter packed (key,idx) into bucket slots. 4 elems/thread for ILP. 64 x 256.
__global__ void __launch_bounds__(256)
k3_scatter(const float* __restrict__ rank) {
    int base = (blockIdx.x * 256 + threadIdx.x) * 4;
#pragma unroll
    for (int j = 0; j < 4; j++) {
        int i = base + j;
        float k = rank[i];
        unsigned b = bucket_of(k);
        unsigned slot = g_off[b] + atomicAdd(&g_cnt[b], 1u);
        g_bsort[slot] = ((unsigned long long)__float_as_uint(k) << 32) | (unsigned)i;
    }
}

// K4: within-bucket order by u64 (key,idx) total order; keys cached locally. 256 x 256.
__global__ void __launch_bounds__(256)
k4_place() {
    int b = blockIdx.x * 256 + threadIdx.x;
    unsigned c = g_hist[b];
    if (c == 0) return;
    unsigned base = g_off[b];
    if (c == 1) {
        unsigned idx = (unsigned)(g_bsort[base] & 0xFFFFFFFFu);
        g_se2[base] = g_e2[idx];
        g_se3[base] = g_e3[idx];
        return;
    }
    if (c <= 16) {
        unsigned long long loc[16];
        for (unsigned j = 0; j < c; j++) loc[j] = g_bsort[base + j];
        for (unsigned j = 0; j < c; j++) {
            unsigned long long kj = loc[j];
            unsigned r = 0;
            for (unsigned l = 0; l < c; l++) r += (loc[l] < kj);  // u64 unique -> strict
            unsigned idx = (unsigned)(kj & 0xFFFFFFFFu);
            g_se2[base + r] = g_e2[idx];
            g_se3[base + r] = g_e3[idx];
        }
    } else {  // rare fallback (bucket count > 16): reads hit L2
        for (unsigned j = 0; j < c; j++) {
            unsigned long long kj = g_bsort[base + j];
            unsigned r = 0;
            for (unsigned l = 0; l < c; l++) r += (g_bsort[base + l] < kj);
            unsigned idx = (unsigned)(kj & 0xFFFFFFFFu);
            g_se2[base + r] = g_e2[idx];
            g_se3[base + r] = g_e3[idx];
        }
    }
}

// K5: per-chunk double sums of both sorted arrays. 256 x 256, shuffle reduce.
__global__ void __launch_bounds__(256)
k5_chunksums() {
    int blk = blockIdx.x, t = threadIdx.x;
    double v2 = (double)g_se2[blk * CHUNK + t];
    double v3 = (double)g_se3[blk * CHUNK + t];
#pragma unroll
    for (int o = 16; o > 0; o >>= 1) {
        v2 += __shfl_xor_sync(0xFFFFFFFFu, v2, o);
        v3 += __shfl_xor_sync(0xFFFFFFFFu, v3, o);
    }
    __shared__ double s2[8], s3[8];
    if ((t & 31) == 0) { s2[t >> 5] = v2; s3[t >> 5] = v3; }
    __syncthreads();
    if (t == 0) {
        double a = 0.0, b = 0.0;
        for (int j = 0; j < 8; j++) { a += s2[j]; b += s3[j]; }
        g_csum2[blk] = a; g_csum3[blk] = b;
    }
}

// K6: redundant chunk-offset scan per block + per-chunk prefix + log accumulation
//     + last-block final reduce & output. 256 x 256.
__global__ void __launch_bounds__(256)
k6_logsum(float* __restrict__ out) {
    int blk = blockIdx.x, t = threadIdx.x;

    // Redundant inclusive scan of 256 chunk sums (both arrays).
    __shared__ double c2[NCHUNK], c3[NCHUNK];
    c2[t] = g_csum2[t]; c3[t] = g_csum3[t];
    __syncthreads();
    for (int o = 1; o < NCHUNK; o <<= 1) {
        double a2 = (t >= o) ? c2[t - o] : 0.0;
        double a3 = (t >= o) ? c3[t - o] : 0.0;
        __syncthreads();
        c2[t] += a2; c3[t] += a3;
        __syncthreads();
    }
    double tot2 = c2[NCHUNK - 1], tot3 = c3[NCHUNK - 1];
    double off2 = (blk > 0) ? c2[blk - 1] : 0.0;
    double off3 = (blk > 0) ? c3[blk - 1] : 0.0;

    // Per-chunk inclusive scan of e values (both arrays together).
    __shared__ double d2[CHUNK], d3[CHUNK];
    int i = blk * CHUNK + t;
    d2[t] = (double)g_se2[i]; d3[t] = (double)g_se3[i];
    __syncthreads();
    for (int o = 1; o < CHUNK; o <<= 1) {
        double a = (t >= o) ? d2[t - o] : 0.0;
        double b = (t >= o) ? d3[t - o] : 0.0;
        __syncthreads();
        d2[t] += a; d3[t] += b;
        __syncthreads();
    }
    double ls = (double)logf((float)(off2 + d2[t])) +
                (double)logf((float)(off3 + d3[t]));

    // Block reduce of log-sum.
#pragma unroll
    for (int o = 16; o > 0; o >>= 1) ls += __shfl_xor_sync(0xFFFFFFFFu, ls, o);
    __shared__ double sr[8];
    if ((t & 31) == 0) sr[t >> 5] = ls;
    __syncthreads();
    if (t == 0) {
        double a = 0.0;
        for (int j = 0; j < 8; j++) a += sr[j];
        g_part[blk] = a;
    }

    // Last block finishes: loss = N*(log tot2 + log tot3) - sum(parts).
    __shared__ bool amLast;
    if (t == 0) {
        __threadfence();
        amLast = (atomicAdd(&g_done, 1u) == NCHUNK - 1);
    }
    __syncthreads();
    if (amLast) {
        double p = g_part[t];
#pragma unroll
        for (int o = 16; o > 0; o >>= 1) p += __shfl_xor_sync(0xFFFFFFFFu, p, o);
        __shared__ double fr[8];
        if ((t & 31) == 0) fr[t >> 5] = p;
        __syncthreads();
        if (t == 0) {
            double s = 0.0;
            for (int j = 0; j < 8; j++) s += fr[j];
            double loss = (double)N_ROWS * (log(tot2) + log(tot3)) - s;
            out[0] = (float)loss;
        }
    }
}

extern "C" void kernel_launch(void* const* d_in, const int* in_sizes, int n_in,
                              void* d_out, int out_size) {
    const float* o1   = (const float*)d_in[0];  // [65536, 512]
    const float* o2   = (const float*)d_in[1];  // [1, 512]
    const float* o3   = (const float*)d_in[2];  // [1, 512]
    const float* rank = (const float*)d_in[3];  // [65536]
    float* out = (float*)d_out;

    k0_init<<<64, 1024>>>((const float4*)o2, (const float4*)o3);
    k1_main<<<N_ROWS / 8, 256>>>((const float4*)o1, (const float4*)o2,
                                 (const float4*)o3, rank);
    k2_scan_hist<<<1, 1024>>>();
    k3_scatter<<<64, 256>>>(rank);
    k4_place<<<NB / 256, 256>>>();
    k5_chunksums<<<NCHUNK, CHUNK>>>();
    k6_logsum<<<NCHUNK, CHUNK>>>(out);
}